// round 2
// baseline (speedup 1.0000x reference)
#include <cuda_runtime.h>
#include <math.h>
#include <stdint.h>

#define BB 4
#define NN 1024
#define DD 768
#define HH 12
#define CC 3072
#define C2 1536
#define ROWS (BB*NN)

// ---------------- scratch (device globals; allocation-free) ----------------
__device__ float g_xa[ROWS*DD];      // LN1(x)
__device__ float g_xm[ROWS*DD];      // LN2(x)
__device__ float g_CT[128*NN];       // coef table, rows 0..64 used, rest stay 0
__device__ float g_csum[65];
__device__ float g_R65[BB*128*DD];   // per-b coefficient-reduced xa
__device__ float g_vsum[2*BB*DD];
__device__ float g_w[2*HH];
__device__ float g_attn[BB*DD];
__device__ float g_h[ROWS*CC];       // gelu(xm@W1+b1)
__device__ float g_xgln[ROWS*C2];
__device__ float g_u[ROWS*C2];       // xr * conv(xg)
__device__ float g_xf[ROWS*2*DD];

__device__ __forceinline__ float geluf(float v) {
    return 0.5f * v * (1.0f + erff(v * 0.7071067811865476f));
}

// ---------------- prep: rope coef table + reattn weights ----------------
__global__ void prep_kernel(const float* __restrict__ reattn,
                            const float* __restrict__ rng,
                            const float* __restrict__ rnb) {
    __shared__ float smix[24];
    int tid = threadIdx.x;   // 1024 threads, tid == position i
    float fi = (float)tid;
    float power = (fi - 512.0f) / 512.0f;
    #pragma unroll
    for (int t = 0; t < 16; t++) {
        float inv = powf(10000.0f, -(float)t / 16.0f);
        float fr = fi * inv;
        float c = cosf(fr), s = sinf(fr);
        int u1 = (2*t) & 15, u2 = (2*t+1) & 15;
        // v uses s = 1/sc  ->  base^(-power)
        float sA = powf((2.0f*u1 + 12.8f) / 44.8f, -power);
        float sB = powf((2.0f*u2 + 12.8f) / 44.8f, -power);
        g_CT[(4*t+0)*NN + tid] = sA * c;
        g_CT[(4*t+1)*NN + tid] = sA * s;
        g_CT[(4*t+2)*NN + tid] = sB * c;
        g_CT[(4*t+3)*NN + tid] = sB * s;
    }
    g_CT[64*NN + tid] = 1.0f;
    __syncthreads();
    // column sums of coefs
    int warp = tid >> 5, lane = tid & 31;
    for (int c = warp; c < 65; c += 32) {
        float s = 0.0f;
        for (int q = lane; q < NN; q += 32) s += g_CT[c*NN + q];
        #pragma unroll
        for (int o = 16; o; o >>= 1) s += __shfl_down_sync(0xffffffffu, s, o);
        if (lane == 0) g_csum[c] = s;
    }
    // reattn mixing weights: s == 1 so mix_g = sum_h R[h,g]; w = LN(mix)*rg+rb
    if (tid < 24) {
        int p = tid / 12, g = tid % 12;
        float m = 0.0f;
        for (int h = 0; h < 12; h++) m += reattn[p*144 + h*12 + g];
        smix[tid] = m;
    }
    __syncthreads();
    if (tid < 24) {
        int p = tid / 12;
        float mean = 0.0f, var = 0.0f;
        for (int g = 0; g < 12; g++) mean += smix[p*12+g];
        mean *= (1.0f/12.0f);
        for (int g = 0; g < 12; g++) { float d = smix[p*12+g]-mean; var += d*d; }
        var *= (1.0f/12.0f);
        float rs = rsqrtf(var + 1e-5f);
        g_w[tid] = (smix[tid]-mean)*rs*rng[tid] + rnb[tid];
    }
}

// ---------------- LN of x -> xa (ln1) and xm (ln2), one pass ----------------
__global__ void ln_x_kernel(const float* __restrict__ x,
                            const float* __restrict__ g1, const float* __restrict__ b1,
                            const float* __restrict__ g2, const float* __restrict__ b2) {
    __shared__ float sh1[33], sh2[33];
    int row = blockIdx.x, tid = threadIdx.x;
    const float* xr = x + (size_t)row * DD;
    float s = 0.0f, s2 = 0.0f;
    #pragma unroll
    for (int c = tid; c < DD; c += 256) { float v = xr[c]; s += v; s2 += v*v; }
    int lane = tid & 31, warp = tid >> 5;
    #pragma unroll
    for (int o = 16; o; o >>= 1) { s += __shfl_down_sync(~0u, s, o); s2 += __shfl_down_sync(~0u, s2, o); }
    if (lane == 0) { sh1[warp] = s; sh2[warp] = s2; }
    __syncthreads();
    if (warp == 0) {
        s  = (lane < 8) ? sh1[lane] : 0.0f;
        s2 = (lane < 8) ? sh2[lane] : 0.0f;
        #pragma unroll
        for (int o = 4; o; o >>= 1) { s += __shfl_down_sync(~0u, s, o); s2 += __shfl_down_sync(~0u, s2, o); }
        if (lane == 0) { sh1[32] = s; sh2[32] = s2; }
    }
    __syncthreads();
    float mean = sh1[32] * (1.0f/DD);
    float var  = sh2[32] * (1.0f/DD) - mean*mean;
    float rs = rsqrtf(var + 1e-5f);
    #pragma unroll
    for (int c = tid; c < DD; c += 256) {
        float v = (xr[c] - mean) * rs;
        g_xa[(size_t)row*DD + c] = v * g1[c] + b1[c];
        g_xm[(size_t)row*DD + c] = v * g2[c] + b2[c];
    }
}

// ---------------- LN of gate half of h (width 1536) ----------------
__global__ void ln_g_kernel(const float* __restrict__ gg, const float* __restrict__ gb) {
    __shared__ float sh1[33], sh2[33];
    int row = blockIdx.x, tid = threadIdx.x;
    const float* xr = g_h + (size_t)row * CC + C2;
    float s = 0.0f, s2 = 0.0f;
    #pragma unroll
    for (int c = tid; c < C2; c += 256) { float v = xr[c]; s += v; s2 += v*v; }
    int lane = tid & 31, warp = tid >> 5;
    #pragma unroll
    for (int o = 16; o; o >>= 1) { s += __shfl_down_sync(~0u, s, o); s2 += __shfl_down_sync(~0u, s2, o); }
    if (lane == 0) { sh1[warp] = s; sh2[warp] = s2; }
    __syncthreads();
    if (warp == 0) {
        s  = (lane < 8) ? sh1[lane] : 0.0f;
        s2 = (lane < 8) ? sh2[lane] : 0.0f;
        #pragma unroll
        for (int o = 4; o; o >>= 1) { s += __shfl_down_sync(~0u, s, o); s2 += __shfl_down_sync(~0u, s2, o); }
        if (lane == 0) { sh1[32] = s; sh2[32] = s2; }
    }
    __syncthreads();
    float mean = sh1[32] * (1.0f/C2);
    float var  = sh2[32] * (1.0f/C2) - mean*mean;
    float rs = rsqrtf(var + 1e-5f);
    #pragma unroll
    for (int c = tid; c < C2; c += 256) {
        float v = (xr[c] - mean) * rs;
        g_xgln[(size_t)row*C2 + c] = v * gg[c] + gb[c];
    }
}

// ---------------- generic 128x128x8 fp32 SGEMM w/ epilogue modes ----------------
// mode 0: C = acc
// mode 1: C = gelu(acc + bias[c])
// mode 2: C = resid[r*ldr+c] + scale[c]*(acc + bias[c])
// mode 3: C = acc + bias[c] + resid[r*ldr+c]
__global__ __launch_bounds__(256) void sgemm_kernel(
    const float* __restrict__ A, const float* __restrict__ B, float* __restrict__ C,
    int M, int N, int K, int ldb, int ldc,
    const float* __restrict__ bias, const float* __restrict__ scale,
    const float* __restrict__ resid, int ldr, int mode,
    size_t bStride, size_t cStride)
{
    __shared__ float As[8][128];
    __shared__ float Bs[8][128];
    B += (size_t)blockIdx.z * bStride;
    C += (size_t)blockIdx.z * cStride;
    int tid = threadIdx.x;
    int m0 = blockIdx.y * 128, n0 = blockIdx.x * 128;
    int aRow = tid >> 1, aCol = (tid & 1) * 4;
    int bRow = tid >> 5, bCol = (tid & 31) * 4;
    const float* Ag = A + (size_t)(m0 + aRow) * K + aCol;
    const float* Bg = B + (size_t)bRow * ldb + n0 + bCol;
    float acc[8][8];
    #pragma unroll
    for (int i = 0; i < 8; i++)
        #pragma unroll
        for (int j = 0; j < 8; j++) acc[i][j] = 0.0f;

    int ty = tid >> 4, tx = tid & 15;
    for (int k0 = 0; k0 < K; k0 += 8) {
        float4 av = *(const float4*)(Ag + k0);
        As[aCol+0][aRow] = av.x; As[aCol+1][aRow] = av.y;
        As[aCol+2][aRow] = av.z; As[aCol+3][aRow] = av.w;
        float4 bv = *(const float4*)(Bg + (size_t)k0 * ldb);
        *(float4*)&Bs[bRow][bCol] = bv;
        __syncthreads();
        #pragma unroll
        for (int kk = 0; kk < 8; kk++) {
            float a[8], b[8];
            *(float4*)(a)   = *(const float4*)&As[kk][ty*8];
            *(float4*)(a+4) = *(const float4*)&As[kk][ty*8+4];
            *(float4*)(b)   = *(const float4*)&Bs[kk][tx*8];
            *(float4*)(b+4) = *(const float4*)&Bs[kk][tx*8+4];
            #pragma unroll
            for (int i = 0; i < 8; i++)
                #pragma unroll
                for (int j = 0; j < 8; j++)
                    acc[i][j] += a[i] * b[j];
        }
        __syncthreads();
    }
    #pragma unroll
    for (int i = 0; i < 8; i++) {
        int r = m0 + ty*8 + i;
        #pragma unroll
        for (int j = 0; j < 8; j++) {
            int c = n0 + tx*8 + j;
            float v = acc[i][j];
            if (mode == 1)      v = geluf(v + bias[c]);
            else if (mode == 2) v = resid[(size_t)r*ldr + c] + scale[c] * (v + bias[c]);
            else if (mode == 3) v = v + bias[c] + resid[(size_t)r*ldr + c];
            C[(size_t)r*ldc + c] = v;
        }
    }
}

// ---------------- vsum: rope-reduced V projection ----------------
__global__ void vsum_kernel(const float* __restrict__ Wqkv, const float* __restrict__ bqkv) {
    int p = blockIdx.z, b = blockIdx.y;
    int j = blockIdx.x * 256 + threadIdx.x;   // 0..767
    const float* W  = Wqkv + (size_t)p * DD * (3*DD) + 2*DD;   // V slice
    const float* bv = bqkv + p * (3*DD) + 2*DD;
    const float* R  = g_R65 + (size_t)b * 128 * DD;
    int c = j & 63;
    float acc;
    if (c < 32) {
        int t = c >> 1;
        if ((c & 1) == 0) {
            const float* r1 = R + (size_t)(4*t+0)*DD;
            const float* r2 = R + (size_t)(4*t+1)*DD;
            float a1 = 0.0f, a2 = 0.0f;
            for (int k = 0; k < DD; k++) {
                a1 += W[(size_t)k*(3*DD) + j]     * r1[k];
                a2 += W[(size_t)k*(3*DD) + j + 1] * r2[k];
            }
            acc = a1 - a2 + bv[j]*g_csum[4*t] - bv[j+1]*g_csum[4*t+1];
        } else {
            const float* r1 = R + (size_t)(4*t+2)*DD;
            const float* r2 = R + (size_t)(4*t+3)*DD;
            float a1 = 0.0f, a2 = 0.0f;
            for (int k = 0; k < DD; k++) {
                a1 += W[(size_t)k*(3*DD) + j]     * r1[k];
                a2 += W[(size_t)k*(3*DD) + j - 1] * r2[k];
            }
            acc = a1 + a2 + bv[j]*g_csum[4*t+2] + bv[j-1]*g_csum[4*t+3];
        }
    } else {
        const float* r = R + (size_t)64*DD;
        acc = bv[j] * g_csum[64];
        for (int k = 0; k < DD; k++)
            acc += W[(size_t)k*(3*DD) + j] * r[k];
    }
    g_vsum[((size_t)p*BB + b)*DD + j] = acc;
}

// ---------------- attn vector (constant over sequence) ----------------
__global__ void attnvec_kernel(const float* __restrict__ Wproj, const float* __restrict__ bproj) {
    __shared__ float yv[2*DD];
    int b = blockIdx.x, tid = threadIdx.x;   // 768 threads
    #pragma unroll
    for (int p = 0; p < 2; p++)
        yv[p*DD + tid] = g_w[p*HH + (tid >> 6)] * g_vsum[((size_t)p*BB + b)*DD + tid];
    __syncthreads();
    float acc = 0.0f;
    #pragma unroll
    for (int p = 0; p < 2; p++) {
        acc += bproj[p*DD + tid];
        const float* Wp = Wproj + (size_t)p * DD * DD;
        const float* y = yv + p*DD;
        for (int jj = 0; jj < DD; jj++)
            acc += y[jj] * Wp[(size_t)jj*DD + tid];
    }
    g_attn[(size_t)b*DD + tid] = acc;
}

// ---------------- xf left half: x + ls1*attn ----------------
__global__ void fill_left_kernel(const float* __restrict__ x, const float* __restrict__ ls1) {
    int c = blockIdx.x * 256 + threadIdx.x;
    int row = blockIdx.y;
    int b = row >> 10;
    g_xf[(size_t)row*(2*DD) + c] = x[(size_t)row*DD + c] + ls1[c] * g_attn[(size_t)b*DD + c];
}

// ---------------- depthwise conv (K=21) + gate multiply ----------------
__global__ void conv_kernel(const float* __restrict__ cw, const float* __restrict__ cb) {
    __shared__ float scw[256*21];
    int ch0 = blockIdx.x * 256;
    int tid = threadIdx.x;
    for (int q = tid; q < 256*21; q += 256) scw[q] = cw[(size_t)ch0*21 + q];
    __syncthreads();
    int ch = ch0 + tid;
    int row = blockIdx.y, b = row >> 10, i = row & 1023;
    float acc = cb[ch];
    #pragma unroll
    for (int k = 0; k < 21; k++) {
        int ii = i + k - 10;
        if (ii >= 0 && ii < NN)
            acc += scw[tid*21 + k] * g_xgln[((size_t)(b << 10) + ii)*C2 + ch];
    }
    g_u[(size_t)row*C2 + ch] = g_h[(size_t)row*CC + ch] * acc;
}

// ---------------- launch ----------------
extern "C" void kernel_launch(void* const* d_in, const int* in_sizes, int n_in,
                              void* d_out, int out_size) {
    const float* x      = (const float*)d_in[0];
    const float* Wqkv   = (const float*)d_in[1];
    const float* bqkv   = (const float*)d_in[2];
    const float* Wproj  = (const float*)d_in[3];
    const float* bproj  = (const float*)d_in[4];
    const float* reattn = (const float*)d_in[9];
    const float* rn_g   = (const float*)d_in[10];
    const float* rn_b   = (const float*)d_in[11];
    const float* ln1_g  = (const float*)d_in[12];
    const float* ln1_b  = (const float*)d_in[13];
    const float* ln2_g  = (const float*)d_in[14];
    const float* ln2_b  = (const float*)d_in[15];
    const float* ls1    = (const float*)d_in[16];
    const float* ls2    = (const float*)d_in[17];
    const float* W1     = (const float*)d_in[18];
    const float* b1     = (const float*)d_in[19];
    const float* gn_g   = (const float*)d_in[20];
    const float* gn_b   = (const float*)d_in[21];
    const float* conv_w = (const float*)d_in[22];
    const float* conv_b = (const float*)d_in[23];
    const float* W2     = (const float*)d_in[24];
    const float* b2     = (const float*)d_in[25];
    const float* Wout   = (const float*)d_in[26];
    const float* bout   = (const float*)d_in[27];
    float* out = (float*)d_out;

    float *xa, *xm, *CT, *R65, *hbuf, *xgln, *ubuf, *xf;
    cudaGetSymbolAddress((void**)&xa,   g_xa);
    cudaGetSymbolAddress((void**)&xm,   g_xm);
    cudaGetSymbolAddress((void**)&CT,   g_CT);
    cudaGetSymbolAddress((void**)&R65,  g_R65);
    cudaGetSymbolAddress((void**)&hbuf, g_h);
    cudaGetSymbolAddress((void**)&xgln, g_xgln);
    cudaGetSymbolAddress((void**)&ubuf, g_u);
    cudaGetSymbolAddress((void**)&xf,   g_xf);

    // rope/coef tables + reattn weights
    prep_kernel<<<1, 1024>>>(reattn, rn_g, rn_b);
    // LN1 + LN2 of x
    ln_x_kernel<<<ROWS, 256>>>(x, ln1_g, ln1_b, ln2_g, ln2_b);
    // R65[b] = CT(65x1024, padded 128) @ xa[b](1024x768)
    sgemm_kernel<<<dim3(6,1,4), 256>>>(CT, xa, R65, 128, DD, NN, DD, DD,
                                       nullptr, nullptr, nullptr, 0, 0,
                                       (size_t)NN*DD, (size_t)128*DD);
    // vsum per path
    vsum_kernel<<<dim3(3,4,2), 256>>>(Wqkv, bqkv);
    // attn constant vector per batch
    attnvec_kernel<<<4, 768>>>(Wproj, bproj);
    // xf[:, :768] = x + ls1*attn
    fill_left_kernel<<<dim3(3, ROWS), 256>>>(x, ls1);
    // h = gelu(xm @ W1 + b1)
    sgemm_kernel<<<dim3(CC/128, ROWS/128, 1), 256>>>(xm, W1, hbuf, ROWS, CC, DD, CC, CC,
                                                     b1, nullptr, nullptr, 0, 1, 0, 0);
    // LN over gate half
    ln_g_kernel<<<ROWS, 256>>>(gn_g, gn_b);
    // depthwise conv + gate
    conv_kernel<<<dim3(6, ROWS), 256>>>(conv_w, conv_b);
    // xf[:, 768:] = x + ls2*(u @ W2 + b2)
    sgemm_kernel<<<dim3(DD/128, ROWS/128, 1), 256>>>(ubuf, W2, xf + DD, ROWS, DD, C2, DD, 2*DD,
                                                     b2, ls2, x, DD, 2, 0, 0);
    // out = xf @ Wout + bout + x
    sgemm_kernel<<<dim3(DD/128, ROWS/128, 1), 256>>>(xf, Wout, out, ROWS, DD, 2*DD, DD, DD,
                                                     bout, nullptr, x, DD, 3, 0, 0);
}

// round 6
// speedup vs baseline: 1.9930x; 1.9930x over previous
#include <cuda_runtime.h>
#include <cuda_bf16.h>
#include <math.h>
#include <stdint.h>

#define BB 4
#define NN 1024
#define DD 768
#define HH 12
#define CC 3072
#define C2 1536
#define ROWS (BB*NN)

// ---------------- fp32 scratch ----------------
__device__ float g_xa[ROWS*DD];
__device__ float g_CT[128*NN];
__device__ float g_csum[65];
__device__ float g_R65[BB*128*DD];
__device__ float g_wvt[2*DD*DD];     // transposed V-slice of Wqkv, fp32
__device__ float g_vsum[2*BB*DD];
__device__ float g_w[2*HH];
__device__ float g_attn[BB*DD];
__device__ float g_h[ROWS*CC];
__device__ float g_xgln[ROWS*C2];

// ---------------- bf16 hi/lo split buffers ----------------
__device__ __align__(16) __nv_bfloat16 g_xmh[ROWS*DD], g_xml[ROWS*DD];
__device__ __align__(16) __nv_bfloat16 g_w1h[CC*DD],   g_w1l[CC*DD];
__device__ __align__(16) __nv_bfloat16 g_w2h[DD*C2],   g_w2l[DD*C2];
__device__ __align__(16) __nv_bfloat16 g_woh[DD*2*DD], g_wol[DD*2*DD];
__device__ __align__(16) __nv_bfloat16 g_uh[ROWS*C2],  g_ul[ROWS*C2];
__device__ __align__(16) __nv_bfloat16 g_xfh[ROWS*2*DD], g_xfl[ROWS*2*DD];

__device__ __forceinline__ float geluf(float v) {
    return 0.5f * v * (1.0f + erff(v * 0.7071067811865476f));
}
__device__ __forceinline__ void split_bf16(float v, __nv_bfloat16& h, __nv_bfloat16& l) {
    h = __float2bfloat16(v);
    l = __float2bfloat16(v - __bfloat162float(h));
}

// ================= mma.sync helpers (plain sm_80+ features; no 'a' target needed) ====
__device__ __forceinline__ void ldsm_x4(uint32_t& r0, uint32_t& r1, uint32_t& r2, uint32_t& r3, uint32_t a) {
    asm volatile("ldmatrix.sync.aligned.m8n8.x4.shared.b16 {%0,%1,%2,%3}, [%4];"
        : "=r"(r0), "=r"(r1), "=r"(r2), "=r"(r3) : "r"(a));
}
__device__ __forceinline__ void mma_bf16(float* d, const uint32_t* a, const uint32_t* b) {
    asm volatile("mma.sync.aligned.m16n8k16.row.col.f32.bf16.bf16.f32 "
        "{%0,%1,%2,%3}, {%4,%5,%6,%7}, {%8,%9}, {%0,%1,%2,%3};"
        : "+f"(d[0]), "+f"(d[1]), "+f"(d[2]), "+f"(d[3])
        : "r"(a[0]), "r"(a[1]), "r"(a[2]), "r"(a[3]), "r"(b[0]), "r"(b[1]));
}
__device__ __forceinline__ void cp16(uint32_t s, const void* g) {
    asm volatile("cp.async.cg.shared.global [%0], [%1], 16;" :: "r"(s), "l"(g));
}
#define CP_COMMIT() asm volatile("cp.async.commit_group;" ::: "memory")
#define CP_WAIT1()  asm volatile("cp.async.wait_group 1;" ::: "memory")

// ================= split-bf16 GEMM: D = A @ B^T (+epilogue) via mma.sync =============
// A: [M,K] K-major bf16 hi/lo.  B: [N,K] K-major bf16 hi/lo.
// Tile 128x128, K chunk 32, 256 thr, double-buffered cp.async.
// 3 phases: Ah.Bh, Ah.Bl, Al.Bh accumulated in one fp32 acc.
// modes: 1=gelu(acc+bias)->C f32; 2: resid+scale*(acc+bias)->bf16 split Cbh/Cbl;
//        3: acc+bias+resid -> C f32.
#define SROW 40   // padded row stride in bf16 elems (80B: conflict-free ldmatrix)
__global__ __launch_bounds__(256) void mma_gemm(
    const __nv_bfloat16* __restrict__ Ah, const __nv_bfloat16* __restrict__ Al,
    const __nv_bfloat16* __restrict__ Bh, const __nv_bfloat16* __restrict__ Bl,
    int K,
    float* __restrict__ C, int ldc,
    __nv_bfloat16* __restrict__ Cbh, __nv_bfloat16* __restrict__ Cbl, int ldcb,
    const float* __restrict__ bias, const float* __restrict__ scale,
    const float* __restrict__ resid, int ldr, int mode)
{
    __shared__ __align__(16) __nv_bfloat16 sA[2][128*SROW];
    __shared__ __align__(16) __nv_bfloat16 sB[2][128*SROW];
    const int tid = threadIdx.x, lane = tid & 31, wid = tid >> 5;
    const int m0 = blockIdx.y * 128, n0 = blockIdx.x * 128;
    const int wm = wid >> 1, wn = wid & 1;            // 4x2 warp grid
    const int mb = wm * 32, nb = wn * 64;

    float acc[2][8][4];
    #pragma unroll
    for (int i = 0; i < 2; i++)
        #pragma unroll
        for (int j = 0; j < 8; j++)
            #pragma unroll
            for (int q = 0; q < 4; q++) acc[i][j][q] = 0.0f;

    const int kSteps = K >> 5, nIter = 3 * kSteps;
    const int lr = tid >> 2, lc = (tid & 3) * 8;      // cp.async mapping

    auto loadStage = [&](int iter, int st) {
        int ph = iter / kSteps, kc = iter % kSteps;
        const __nv_bfloat16* A = (ph < 2) ? Ah : Al;
        const __nv_bfloat16* B = (ph == 1) ? Bl : Bh;
        int k0 = kc << 5;
        uint32_t sa = (uint32_t)__cvta_generic_to_shared(&sA[st][0]);
        uint32_t sb = (uint32_t)__cvta_generic_to_shared(&sB[st][0]);
        cp16(sa + (lr*SROW + lc)*2,        A + (size_t)(m0 + lr)      * K + k0 + lc);
        cp16(sa + ((lr+64)*SROW + lc)*2,   A + (size_t)(m0 + lr + 64) * K + k0 + lc);
        cp16(sb + (lr*SROW + lc)*2,        B + (size_t)(n0 + lr)      * K + k0 + lc);
        cp16(sb + ((lr+64)*SROW + lc)*2,   B + (size_t)(n0 + lr + 64) * K + k0 + lc);
    };

    loadStage(0, 0);
    CP_COMMIT();
    for (int i = 0; i < nIter; i++) {
        if (i + 1 < nIter) loadStage(i + 1, (i + 1) & 1);
        CP_COMMIT();
        CP_WAIT1();
        __syncthreads();
        int st = i & 1;
        uint32_t sa = (uint32_t)__cvta_generic_to_shared(&sA[st][0]);
        uint32_t sb = (uint32_t)__cvta_generic_to_shared(&sB[st][0]);
        #pragma unroll
        for (int ks = 0; ks < 2; ks++) {
            int kl = ks * 16;
            uint32_t af[2][4];
            #pragma unroll
            for (int mt = 0; mt < 2; mt++) {
                int row = mb + mt*16 + (lane & 15);
                int ko  = kl + ((lane >> 4) << 3);
                ldsm_x4(af[mt][0], af[mt][1], af[mt][2], af[mt][3],
                        sa + (uint32_t)(row*SROW + ko)*2);
            }
            uint32_t bf[8][2];
            #pragma unroll
            for (int nt4 = 0; nt4 < 4; nt4++) {
                int nrow = nb + nt4*16 + (lane & 7) + ((lane >> 4) << 3);
                int ko   = kl + (((lane >> 3) & 1) << 3);
                uint32_t r0, r1, r2, r3;
                ldsm_x4(r0, r1, r2, r3, sb + (uint32_t)(nrow*SROW + ko)*2);
                bf[nt4*2][0] = r0; bf[nt4*2][1] = r1;
                bf[nt4*2+1][0] = r2; bf[nt4*2+1][1] = r3;
            }
            #pragma unroll
            for (int mt = 0; mt < 2; mt++)
                #pragma unroll
                for (int nt = 0; nt < 8; nt++)
                    mma_bf16(acc[mt][nt], af[mt], bf[nt]);
        }
        __syncthreads();
    }

    // epilogue
    #pragma unroll
    for (int mt = 0; mt < 2; mt++) {
        #pragma unroll
        for (int nt = 0; nt < 8; nt++) {
            int row = m0 + mb + mt*16 + (lane >> 2);
            int col = n0 + nb + nt*8 + (lane & 3)*2;
            #pragma unroll
            for (int h = 0; h < 2; h++) {       // row, row+8
                int rr = row + h*8;
                #pragma unroll
                for (int q = 0; q < 2; q++) {   // col, col+1
                    int cc = col + q;
                    float v = acc[mt][nt][h*2 + q];
                    if (mode == 1) {
                        C[(size_t)rr*ldc + cc] = geluf(v + bias[cc]);
                    } else if (mode == 2) {
                        float o = resid[(size_t)rr*ldr + cc] + scale[cc]*(v + bias[cc]);
                        __nv_bfloat16 hh, ll; split_bf16(o, hh, ll);
                        Cbh[(size_t)rr*ldcb + cc] = hh;
                        Cbl[(size_t)rr*ldcb + cc] = ll;
                    } else {
                        C[(size_t)rr*ldc + cc] = v + bias[cc] + resid[(size_t)rr*ldr + cc];
                    }
                }
            }
        }
    }
}

// ================= weight split+transpose: W[K,N] f32 -> Wh/Wl[N,K] bf16 =================
__global__ void wsplit_kernel(const float* __restrict__ W,
                              __nv_bfloat16* __restrict__ Wh, __nv_bfloat16* __restrict__ Wl,
                              int K, int N) {
    __shared__ float t[32][33];
    int n0 = blockIdx.x * 32, k0 = blockIdx.y * 32;
    int tx = threadIdx.x, ty = threadIdx.y;
    for (int i = ty; i < 32; i += 8) t[i][tx] = W[(size_t)(k0 + i) * N + n0 + tx];
    __syncthreads();
    for (int i = ty; i < 32; i += 8) {
        float v = t[tx][i];
        __nv_bfloat16 h, l; split_bf16(v, h, l);
        Wh[(size_t)(n0 + i) * K + k0 + tx] = h;
        Wl[(size_t)(n0 + i) * K + k0 + tx] = l;
    }
}

// Wv transpose fp32: g_wvt[p][j][k] = Wqkv[p][k][1536+j]
__global__ void wvt_kernel(const float* __restrict__ Wqkv) {
    __shared__ float t[32][33];
    int p = blockIdx.z;
    const float* W = Wqkv + (size_t)p * DD * (3*DD) + 2*DD;
    int j0 = blockIdx.x * 32, k0 = blockIdx.y * 32;
    int tx = threadIdx.x, ty = threadIdx.y;
    for (int i = ty; i < 32; i += 8) t[i][tx] = W[(size_t)(k0 + i) * (3*DD) + j0 + tx];
    __syncthreads();
    for (int i = ty; i < 32; i += 8)
        g_wvt[(size_t)p * DD * DD + (size_t)(j0 + i) * DD + k0 + tx] = t[tx][i];
}

// ---------------- prep: rope coef table + reattn weights ----------------
__global__ void prep_kernel(const float* __restrict__ reattn,
                            const float* __restrict__ rng,
                            const float* __restrict__ rnb) {
    __shared__ float smix[24];
    int tid = threadIdx.x;
    float fi = (float)tid;
    float power = (fi - 512.0f) / 512.0f;
    #pragma unroll
    for (int t = 0; t < 16; t++) {
        float inv = powf(10000.0f, -(float)t / 16.0f);
        float fr = fi * inv;
        float c = cosf(fr), s = sinf(fr);
        int u1 = (2*t) & 15, u2 = (2*t+1) & 15;
        float sA = powf((2.0f*u1 + 12.8f) / 44.8f, -power);
        float sB = powf((2.0f*u2 + 12.8f) / 44.8f, -power);
        g_CT[(4*t+0)*NN + tid] = sA * c;
        g_CT[(4*t+1)*NN + tid] = sA * s;
        g_CT[(4*t+2)*NN + tid] = sB * c;
        g_CT[(4*t+3)*NN + tid] = sB * s;
    }
    g_CT[64*NN + tid] = 1.0f;
    __syncthreads();
    int warp = tid >> 5, lane = tid & 31;
    for (int c = warp; c < 65; c += 32) {
        float s = 0.0f;
        for (int q = lane; q < NN; q += 32) s += g_CT[c*NN + q];
        #pragma unroll
        for (int o = 16; o; o >>= 1) s += __shfl_down_sync(0xffffffffu, s, o);
        if (lane == 0) g_csum[c] = s;
    }
    if (tid < 24) {
        int p = tid / 12, g = tid % 12;
        float m = 0.0f;
        for (int h = 0; h < 12; h++) m += reattn[p*144 + h*12 + g];
        smix[tid] = m;
    }
    __syncthreads();
    if (tid < 24) {
        int p = tid / 12;
        float mean = 0.0f, var = 0.0f;
        for (int g = 0; g < 12; g++) mean += smix[p*12+g];
        mean *= (1.0f/12.0f);
        for (int g = 0; g < 12; g++) { float d = smix[p*12+g]-mean; var += d*d; }
        var *= (1.0f/12.0f);
        float rs = rsqrtf(var + 1e-5f);
        g_w[tid] = (smix[tid]-mean)*rs*rng[tid] + rnb[tid];
    }
}

// ---------------- LN of x -> xa (f32) and xm (bf16 hi/lo) ----------------
__global__ void ln_x_kernel(const float* __restrict__ x,
                            const float* __restrict__ g1, const float* __restrict__ b1,
                            const float* __restrict__ g2, const float* __restrict__ b2) {
    __shared__ float sh1[33], sh2[33];
    int row = blockIdx.x, tid = threadIdx.x;
    const float* xr = x + (size_t)row * DD;
    float s = 0.0f, s2 = 0.0f;
    #pragma unroll
    for (int c = tid; c < DD; c += 256) { float v = xr[c]; s += v; s2 += v*v; }
    int lane = tid & 31, warp = tid >> 5;
    #pragma unroll
    for (int o = 16; o; o >>= 1) { s += __shfl_down_sync(~0u, s, o); s2 += __shfl_down_sync(~0u, s2, o); }
    if (lane == 0) { sh1[warp] = s; sh2[warp] = s2; }
    __syncthreads();
    if (warp == 0) {
        s  = (lane < 8) ? sh1[lane] : 0.0f;
        s2 = (lane < 8) ? sh2[lane] : 0.0f;
        #pragma unroll
        for (int o = 4; o; o >>= 1) { s += __shfl_down_sync(~0u, s, o); s2 += __shfl_down_sync(~0u, s2, o); }
        if (lane == 0) { sh1[32] = s; sh2[32] = s2; }
    }
    __syncthreads();
    float mean = sh1[32] * (1.0f/DD);
    float var  = sh2[32] * (1.0f/DD) - mean*mean;
    float rs = rsqrtf(var + 1e-5f);
    #pragma unroll
    for (int c = tid; c < DD; c += 256) {
        float v = (xr[c] - mean) * rs;
        g_xa[(size_t)row*DD + c] = v * g1[c] + b1[c];
        float m = v * g2[c] + b2[c];
        __nv_bfloat16 h, l; split_bf16(m, h, l);
        g_xmh[(size_t)row*DD + c] = h;
        g_xml[(size_t)row*DD + c] = l;
    }
}

// ---------------- LN of gate half of h ----------------
__global__ void ln_g_kernel(const float* __restrict__ gg, const float* __restrict__ gb) {
    __shared__ float sh1[33], sh2[33];
    int row = blockIdx.x, tid = threadIdx.x;
    const float* xr = g_h + (size_t)row * CC + C2;
    float s = 0.0f, s2 = 0.0f;
    #pragma unroll
    for (int c = tid; c < C2; c += 256) { float v = xr[c]; s += v; s2 += v*v; }
    int lane = tid & 31, warp = tid >> 5;
    #pragma unroll
    for (int o = 16; o; o >>= 1) { s += __shfl_down_sync(~0u, s, o); s2 += __shfl_down_sync(~0u, s2, o); }
    if (lane == 0) { sh1[warp] = s; sh2[warp] = s2; }
    __syncthreads();
    if (warp == 0) {
        s  = (lane < 8) ? sh1[lane] : 0.0f;
        s2 = (lane < 8) ? sh2[lane] : 0.0f;
        #pragma unroll
        for (int o = 4; o; o >>= 1) { s += __shfl_down_sync(~0u, s, o); s2 += __shfl_down_sync(~0u, s2, o); }
        if (lane == 0) { sh1[32] = s; sh2[32] = s2; }
    }
    __syncthreads();
    float mean = sh1[32] * (1.0f/C2);
    float var  = sh2[32] * (1.0f/C2) - mean*mean;
    float rs = rsqrtf(var + 1e-5f);
    #pragma unroll
    for (int c = tid; c < C2; c += 256) {
        float v = (xr[c] - mean) * rs;
        g_xgln[(size_t)row*C2 + c] = v * gg[c] + gb[c];
    }
}

// ---------------- fp32 SGEMM (only used for the small R65 reduction) ----------------
__global__ __launch_bounds__(256) void sgemm_kernel(
    const float* __restrict__ A, const float* __restrict__ B, float* __restrict__ C,
    int K, int ldb, int ldc, size_t bStride, size_t cStride)
{
    __shared__ float As[8][128];
    __shared__ float Bs[8][128];
    B += (size_t)blockIdx.z * bStride;
    C += (size_t)blockIdx.z * cStride;
    int tid = threadIdx.x;
    int m0 = blockIdx.y * 128, n0 = blockIdx.x * 128;
    int aRow = tid >> 1, aCol = (tid & 1) * 4;
    int bRow = tid >> 5, bCol = (tid & 31) * 4;
    const float* Ag = A + (size_t)(m0 + aRow) * K + aCol;
    const float* Bg = B + (size_t)bRow * ldb + n0 + bCol;
    float acc[8][8];
    #pragma unroll
    for (int i = 0; i < 8; i++)
        #pragma unroll
        for (int j = 0; j < 8; j++) acc[i][j] = 0.0f;
    int ty = tid >> 4, tx = tid & 15;
    for (int k0 = 0; k0 < K; k0 += 8) {
        float4 av = *(const float4*)(Ag + k0);
        As[aCol+0][aRow] = av.x; As[aCol+1][aRow] = av.y;
        As[aCol+2][aRow] = av.z; As[aCol+3][aRow] = av.w;
        float4 bv = *(const float4*)(Bg + (size_t)k0 * ldb);
        *(float4*)&Bs[bRow][bCol] = bv;
        __syncthreads();
        #pragma unroll
        for (int kk = 0; kk < 8; kk++) {
            float a[8], b[8];
            *(float4*)(a)   = *(const float4*)&As[kk][ty*8];
            *(float4*)(a+4) = *(const float4*)&As[kk][ty*8+4];
            *(float4*)(b)   = *(const float4*)&Bs[kk][tx*8];
            *(float4*)(b+4) = *(const float4*)&Bs[kk][tx*8+4];
            #pragma unroll
            for (int i = 0; i < 8; i++)
                #pragma unroll
                for (int j = 0; j < 8; j++)
                    acc[i][j] += a[i] * b[j];
        }
        __syncthreads();
    }
    #pragma unroll
    for (int i = 0; i < 8; i++) {
        int r = m0 + ty*8 + i;
        #pragma unroll
        for (int j = 0; j < 8; j++)
            C[(size_t)r*ldc + n0 + tx*8 + j] = acc[i][j];
    }
}

// ---------------- vsum: warp-per-output using transposed Wv ----------------
__global__ void vsum2_kernel(const float* __restrict__ bqkv) {
    int gw = (blockIdx.x * blockDim.x + threadIdx.x) >> 5;
    int lane = threadIdx.x & 31;
    int j = gw % DD;
    int b = (gw / DD) & 3;
    int p = gw / (4 * DD);
    const float* bv = bqkv + p * (3*DD) + 2*DD;
    const float* R  = g_R65 + (size_t)b * 128 * DD;
    const float* Wt = g_wvt + (size_t)p * DD * DD;
    int c = j & 63;
    float acc = 0.0f;
    if (c < 32) {
        int t = c >> 1;
        int r1, r2, j2; float sgn;
        if (!(c & 1)) { r1 = 4*t;   r2 = 4*t+1; j2 = j+1; sgn = -1.0f; }
        else          { r1 = 4*t+2; r2 = 4*t+3; j2 = j-1; sgn =  1.0f; }
        const float* R1 = R + (size_t)r1 * DD;
        const float* R2 = R + (size_t)r2 * DD;
        const float* Wa = Wt + (size_t)j  * DD;
        const float* Wb = Wt + (size_t)j2 * DD;
        float a1 = 0.0f, a2 = 0.0f;
        for (int k = lane; k < DD; k += 32) { a1 += Wa[k]*R1[k]; a2 += Wb[k]*R2[k]; }
        acc = a1 + sgn * a2;
        #pragma unroll
        for (int o = 16; o; o >>= 1) acc += __shfl_down_sync(~0u, acc, o);
        if (lane == 0) acc += bv[j]*g_csum[r1] + sgn*bv[j2]*g_csum[r2];
    } else {
        const float* Rr = R + (size_t)64 * DD;
        const float* Wa = Wt + (size_t)j * DD;
        float a = 0.0f;
        for (int k = lane; k < DD; k += 32) a += Wa[k]*Rr[k];
        #pragma unroll
        for (int o = 16; o; o >>= 1) a += __shfl_down_sync(~0u, a, o);
        if (lane == 0) acc = a + bv[j]*g_csum[64];
    }
    if (lane == 0) g_vsum[((size_t)p*BB + b)*DD + j] = acc;
}

// ---------------- attn vector (constant over sequence) ----------------
__global__ void attnvec_kernel(const float* __restrict__ Wproj, const float* __restrict__ bproj) {
    __shared__ float yv[2*DD];
    int b = blockIdx.x, tid = threadIdx.x;
    #pragma unroll
    for (int p = 0; p < 2; p++)
        yv[p*DD + tid] = g_w[p*HH + (tid >> 6)] * g_vsum[((size_t)p*BB + b)*DD + tid];
    __syncthreads();
    float acc = 0.0f;
    #pragma unroll
    for (int p = 0; p < 2; p++) {
        acc += bproj[p*DD + tid];
        const float* Wp = Wproj + (size_t)p * DD * DD;
        const float* y = yv + p*DD;
        for (int jj = 0; jj < DD; jj++)
            acc += y[jj] * Wp[(size_t)jj*DD + tid];
    }
    g_attn[(size_t)b*DD + tid] = acc;
}

// ---------------- xf left half: x + ls1*attn -> bf16 hi/lo ----------------
__global__ void fill_left_kernel(const float* __restrict__ x, const float* __restrict__ ls1) {
    int c = blockIdx.x * 256 + threadIdx.x;
    int row = blockIdx.y;
    int b = row >> 10;
    float v = x[(size_t)row*DD + c] + ls1[c] * g_attn[(size_t)b*DD + c];
    __nv_bfloat16 h, l; split_bf16(v, h, l);
    g_xfh[(size_t)row*(2*DD) + c] = h;
    g_xfl[(size_t)row*(2*DD) + c] = l;
}

// ---------------- depthwise conv (K=21) + gate -> u bf16 hi/lo ----------------
__global__ void conv_kernel(const float* __restrict__ cw, const float* __restrict__ cb) {
    __shared__ float scw[256*21];
    int ch0 = blockIdx.x * 256;
    int tid = threadIdx.x;
    for (int q = tid; q < 256*21; q += 256) scw[q] = cw[(size_t)ch0*21 + q];
    __syncthreads();
    int ch = ch0 + tid;
    int row = blockIdx.y, b = row >> 10, i = row & 1023;
    float acc = cb[ch];
    #pragma unroll
    for (int k = 0; k < 21; k++) {
        int ii = i + k - 10;
        if (ii >= 0 && ii < NN)
            acc += scw[tid*21 + k] * g_xgln[((size_t)(b << 10) + ii)*C2 + ch];
    }
    float v = g_h[(size_t)row*CC + ch] * acc;
    __nv_bfloat16 h, l; split_bf16(v, h, l);
    g_uh[(size_t)row*C2 + ch] = h;
    g_ul[(size_t)row*C2 + ch] = l;
}

// ---------------- launch ----------------
extern "C" void kernel_launch(void* const* d_in, const int* in_sizes, int n_in,
                              void* d_out, int out_size) {
    const float* x      = (const float*)d_in[0];
    const float* Wqkv   = (const float*)d_in[1];
    const float* bqkv   = (const float*)d_in[2];
    const float* Wproj  = (const float*)d_in[3];
    const float* bproj  = (const float*)d_in[4];
    const float* reattn = (const float*)d_in[9];
    const float* rn_g   = (const float*)d_in[10];
    const float* rn_b   = (const float*)d_in[11];
    const float* ln1_g  = (const float*)d_in[12];
    const float* ln1_b  = (const float*)d_in[13];
    const float* ln2_g  = (const float*)d_in[14];
    const float* ln2_b  = (const float*)d_in[15];
    const float* ls1    = (const float*)d_in[16];
    const float* ls2    = (const float*)d_in[17];
    const float* W1     = (const float*)d_in[18];
    const float* b1     = (const float*)d_in[19];
    const float* gn_g   = (const float*)d_in[20];
    const float* gn_b   = (const float*)d_in[21];
    const float* conv_w = (const float*)d_in[22];
    const float* conv_b = (const float*)d_in[23];
    const float* W2     = (const float*)d_in[24];
    const float* b2     = (const float*)d_in[25];
    const float* Wout   = (const float*)d_in[26];
    const float* bout   = (const float*)d_in[27];
    float* out = (float*)d_out;

    float *xa, *CT, *R65, *hbuf;
    __nv_bfloat16 *xmh, *xml, *w1h, *w1l, *w2h, *w2l, *woh, *wol, *uh, *ul, *xfh, *xfl;
    cudaGetSymbolAddress((void**)&xa,   g_xa);
    cudaGetSymbolAddress((void**)&CT,   g_CT);
    cudaGetSymbolAddress((void**)&R65,  g_R65);
    cudaGetSymbolAddress((void**)&hbuf, g_h);
    cudaGetSymbolAddress((void**)&xmh,  g_xmh);  cudaGetSymbolAddress((void**)&xml, g_xml);
    cudaGetSymbolAddress((void**)&w1h,  g_w1h);  cudaGetSymbolAddress((void**)&w1l, g_w1l);
    cudaGetSymbolAddress((void**)&w2h,  g_w2h);  cudaGetSymbolAddress((void**)&w2l, g_w2l);
    cudaGetSymbolAddress((void**)&woh,  g_woh);  cudaGetSymbolAddress((void**)&wol, g_wol);
    cudaGetSymbolAddress((void**)&uh,   g_uh);   cudaGetSymbolAddress((void**)&ul,  g_ul);
    cudaGetSymbolAddress((void**)&xfh,  g_xfh);  cudaGetSymbolAddress((void**)&xfl, g_xfl);

    dim3 t32x8(32, 8);
    // weight prep (independent of activations)
    prep_kernel<<<1, 1024>>>(reattn, rn_g, rn_b);
    wsplit_kernel<<<dim3(CC/32, DD/32), t32x8>>>(W1, w1h, w1l, DD, CC);
    wsplit_kernel<<<dim3(DD/32, C2/32), t32x8>>>(W2, w2h, w2l, C2, DD);
    wsplit_kernel<<<dim3(DD/32, C2/32), t32x8>>>(Wout, woh, wol, C2, DD);
    wvt_kernel<<<dim3(DD/32, DD/32, 2), t32x8>>>(Wqkv);

    // LN1 -> xa f32, LN2 -> xm bf16 split
    ln_x_kernel<<<ROWS, 256>>>(x, ln1_g, ln1_b, ln2_g, ln2_b);

    // attention path (exact fp32, constant over sequence)
    sgemm_kernel<<<dim3(6,1,4), 256>>>(CT, xa, R65, NN, DD, DD,
                                       (size_t)NN*DD, (size_t)128*DD);
    vsum2_kernel<<<768, 256>>>(bqkv);
    attnvec_kernel<<<4, 768>>>(Wproj, bproj);
    fill_left_kernel<<<dim3(3, ROWS), 256>>>(x, ls1);

    // h = gelu(xm @ W1 + b1)   [tensor cores via mma.sync, split bf16]
    mma_gemm<<<dim3(CC/128, ROWS/128), 256>>>(
        xmh, xml, w1h, w1l, DD, hbuf, CC,
        nullptr, nullptr, 0, b1, nullptr, nullptr, 0, 1);
    ln_g_kernel<<<ROWS, 256>>>(gn_g, gn_b);
    conv_kernel<<<dim3(6, ROWS), 256>>>(conv_w, conv_b);
    // xf right half = x + ls2*(u @ W2 + b2)  -> bf16 split into xf[:,768:]
    mma_gemm<<<dim3(DD/128, ROWS/128), 256>>>(
        uh, ul, w2h, w2l, C2, nullptr, 0,
        xfh + DD, xfl + DD, 2*DD, b2, ls2, x, DD, 2);
    // out = xf @ Wout + bout + x
    mma_gemm<<<dim3(DD/128, ROWS/128), 256>>>(
        xfh, xfl, woh, wol, 2*DD, out, DD,
        nullptr, nullptr, 0, bout, nullptr, x, DD, 3);
}